// round 11
// baseline (speedup 1.0000x reference)
#include <cuda_runtime.h>
#include <cuda_fp16.h>
#include <cstdint>

// Problem constants (fixed shapes per reference)
#define DIMC 128
#define KC   65536
#define BC   1024
#define LC   512
#define PC   8388608

// Block-role layout in the single pool
#define NB_TRANS 2048
#define NB_KEYN  128
#define NB_READY (NB_TRANS + NB_KEYN)          // 2176 producers
#define NB_GATHER 1024
#define NB_EMA   (PC / 1024)                   // 8192
#define NB_COPY  2048
// order: [trans | keyN | gather | EMA | copy]
#define BID_GATHER NB_READY
#define BID_EMA    (BID_GATHER + NB_GATHER)
#define BID_COPY   (BID_EMA + NB_EMA)
#define NB_TOTAL   (BID_COPY + NB_COPY)        // 13440

// Scratch (device globals — no allocation allowed)
__device__ __half   g_qTh[(size_t)KC * DIMC];  // 16 MB transposed queue, fp16
__device__ float    g_keysN[BC * DIMC];        // normalized keys
__device__ unsigned g_ctr = 0;                 // producer-completion counter

__device__ __forceinline__ void wait_ready() {
    if (threadIdx.x == 0) {
        while (atomicAdd(&g_ctr, 0u) < (unsigned)NB_READY)
            __nanosleep(64);
        __threadfence();
    }
    __syncthreads();
}

// ---------------------------------------------------------------------------
// Single pool kernel. 13440 blocks x 256 threads.
// ---------------------------------------------------------------------------
__global__ __launch_bounds__(256) void moco_pool_kernel(
        const float* __restrict__ q,
        const int* __restrict__ sidx,
        const float* __restrict__ queue,
        const float* __restrict__ keys,
        const float* __restrict__ pq,
        const float* __restrict__ pk,
        const int* __restrict__ ptrp,
        float* __restrict__ logits,
        float* __restrict__ labels,
        float* __restrict__ new_queue,
        float* __restrict__ new_pk) {
    int bid = blockIdx.x;

    if (bid < NB_TRANS) {
        // ---- transpose producer: 32 k-cols x 128 dims -> fp16 g_qTh ----
        __shared__ float tile[32][129];
        int k0   = bid << 5;
        int lane = threadIdx.x & 31;
        int wy   = threadIdx.x >> 5;

        #pragma unroll
        for (int i = 0; i < 16; ++i) {
            int d = wy * 16 + i;
            tile[lane][d] = __ldg(&queue[(size_t)d * KC + (k0 + lane)]);
        }
        __syncthreads();

        #pragma unroll
        for (int j = 0; j < 4; ++j) {
            int k = wy * 4 + j;
            float v0 = tile[k][4 * lane + 0];
            float v1 = tile[k][4 * lane + 1];
            float v2 = tile[k][4 * lane + 2];
            float v3 = tile[k][4 * lane + 3];
            __half2 h0 = __floats2half2_rn(v0, v1);
            __half2 h1 = __floats2half2_rn(v2, v3);
            uint2 pkt = make_uint2(*reinterpret_cast<unsigned*>(&h0),
                                   *reinterpret_cast<unsigned*>(&h1));
            *reinterpret_cast<uint2*>(&g_qTh[(size_t)(k0 + k) * DIMC + 4 * lane]) = pkt;
        }
        __threadfence();
        __syncthreads();
        if (threadIdx.x == 0) atomicAdd(&g_ctr, 1u);

    } else if (bid < NB_READY) {
        // ---- key-normalize producer: one warp per key row (8 rows/block) ----
        int gw   = (bid - NB_TRANS) * 8 + (threadIdx.x >> 5);   // 0..1023
        int lane = threadIdx.x & 31;
        float4 v = reinterpret_cast<const float4*>(keys + (size_t)gw * DIMC)[lane];
        float s = v.x * v.x + v.y * v.y + v.z * v.z + v.w * v.w;
        #pragma unroll
        for (int o = 16; o > 0; o >>= 1) s += __shfl_xor_sync(0xFFFFFFFFu, s, o);
        float inv = 1.0f / sqrtf(s);
        reinterpret_cast<float4*>(g_keysN + (size_t)gw * DIMC)[lane] =
            make_float4(v.x * inv, v.y * inv, v.z * inv, v.w * inv);
        __threadfence();
        __syncthreads();
        if (threadIdx.x == 0) atomicAdd(&g_ctr, 1u);

    } else if (bid < BID_EMA) {
        // ---- logits gather consumer (R3 proven loop) ----
        int b = bid - BID_GATHER;
        __shared__ float4 qs4[32];
        int tid = threadIdx.x;
        if (tid < 32) {
            float4 v = reinterpret_cast<const float4*>(q + (size_t)b * DIMC)[tid];
            float s = v.x * v.x + v.y * v.y + v.z * v.z + v.w * v.w;
            #pragma unroll
            for (int o = 16; o > 0; o >>= 1) s += __shfl_xor_sync(0xFFFFFFFFu, s, o);
            float inv = 1.0f / sqrtf(s);
            qs4[tid] = make_float4(v.x * inv, v.y * inv, v.z * inv, v.w * inv);
        }
        if (tid == 0) labels[b] = 0.0f;

        wait_ready();   // also covers the qs4 __syncthreads dependency

        int lane    = tid & 31;
        int warp    = tid >> 5;
        int half_id = lane >> 4;
        int subl    = lane & 15;

        float4 qa = qs4[subl * 2];
        float4 qb = qs4[subl * 2 + 1];

        const int* row = sidx + (size_t)b * LC;
        float* lrow = logits + (size_t)b * LC;

        #pragma unroll 4
        for (int l = warp * 2; l < LC; l += 16) {
            int idx = row[l + half_id];
            int4 pkt = reinterpret_cast<const int4*>(g_qTh + (size_t)idx * DIMC)[subl];
            float2 f0 = __half22float2(*reinterpret_cast<__half2*>(&pkt.x));
            float2 f1 = __half22float2(*reinterpret_cast<__half2*>(&pkt.y));
            float2 f2 = __half22float2(*reinterpret_cast<__half2*>(&pkt.z));
            float2 f3 = __half22float2(*reinterpret_cast<__half2*>(&pkt.w));
            float s = f0.x * qa.x + f0.y * qa.y + f1.x * qa.z + f1.y * qa.w
                    + f2.x * qb.x + f2.y * qb.y + f3.x * qb.z + f3.y * qb.w;
            #pragma unroll
            for (int o = 8; o > 0; o >>= 1)
                s += __shfl_xor_sync(0xFFFFFFFFu, s, o);
            if (subl == 0)
                lrow[l + half_id] = s * (1.0f / 0.09f);
        }

    } else if (bid < BID_COPY) {
        // ---- EMA stream: 256 float4s per block (independent) ----
        int i = (bid - BID_EMA) * 256 + (int)threadIdx.x;
        float4 a  = __ldcs(reinterpret_cast<const float4*>(pq) + i);
        float4 b4 = __ldcs(reinterpret_cast<const float4*>(pk) + i);
        float4 r = make_float4(b4.x * 0.7f + a.x * 0.3f,
                               b4.y * 0.7f + a.y * 0.3f,
                               b4.z * 0.7f + a.z * 0.3f,
                               b4.w * 0.7f + a.w * 0.3f);
        __stcs(reinterpret_cast<float4*>(new_pk) + i, r);

    } else {
        // ---- queue copy + enqueue consumer: 1024 float4s per block ----
        wait_ready();   // needs g_keysN

        int ptr = *ptrp;
        int base = (bid - BID_COPY) * 1024 + (int)threadIdx.x;
        #pragma unroll
        for (int g = 0; g < 4; ++g) {
            int i = base + g * 256;
            float4 v = __ldg(reinterpret_cast<const float4*>(queue) + i);
            int e = i << 2;
            int d = e >> 16;          // / K
            int k = e & (KC - 1);     // % K
            float* c = &v.x;
            #pragma unroll
            for (int j = 0; j < 4; ++j) {
                int r = k + j - ptr;
                if ((unsigned)r < (unsigned)BC)
                    c[j] = g_keysN[(size_t)r * DIMC + d];
            }
            __stcs(reinterpret_cast<float4*>(new_queue) + i, v);
        }
    }
}

// ---------------------------------------------------------------------------
extern "C" void kernel_launch(void* const* d_in, const int* in_sizes, int n_in,
                              void* d_out, int out_size) {
    const float* q        = (const float*)d_in[0];
    const float* queue    = (const float*)d_in[1];
    const float* keys     = (const float*)d_in[2];
    const float* param_q  = (const float*)d_in[3];
    const float* param_k  = (const float*)d_in[4];
    const int*   sidx     = (const int*)  d_in[5];
    const int*   ptr      = (const int*)  d_in[6];

    float* out       = (float*)d_out;
    float* logits    = out;                            // B*L = 524288
    float* labels    = logits + (size_t)BC * LC;       // 1024
    float* new_queue = labels + BC;                    // DIM*K = 8388608
    float* new_pk    = new_queue + (size_t)DIMC * KC;  // P = 8388608

    // One launch: [transpose | keyN | gather | EMA | copy] with in-kernel fence
    moco_pool_kernel<<<NB_TOTAL, 256>>>(
        q, sidx, queue, keys, param_q, param_k, ptr,
        logits, labels, new_queue, new_pk);
}

// round 12
// speedup vs baseline: 1.1049x; 1.1049x over previous
#include <cuda_runtime.h>
#include <cuda_fp16.h>
#include <cstdint>

// Problem constants (fixed shapes per reference)
#define DIMC 128
#define KC   65536
#define BC   1024
#define LC   512
#define PC   8388608

// Pool layout: [keyN 128 | trans 2048 | EMA 2048 | gather 1024 | EMA 6144]
#define NB_KEYN   128
#define NB_TRANS  2048
#define NB_EMA1   2048
#define NB_GATHER 1024
#define NB_EMA2   6144
#define BID_TRANS  NB_KEYN                       // 128
#define BID_EMA1   (BID_TRANS + NB_TRANS)        // 2176
#define BID_GATHER (BID_EMA1 + NB_EMA1)          // 4224
#define BID_EMA2   (BID_GATHER + NB_GATHER)      // 5248
#define NB_TOTAL   (BID_EMA2 + NB_EMA2)          // 11392
#define CTR_KEYS   NB_KEYN                       // 128
#define CTR_TRANS  (NB_KEYN + NB_TRANS)          // 2176

// Scratch (device globals — no allocation allowed)
__device__ __half   g_qTh[(size_t)KC * DIMC];   // 16 MB transposed queue, fp16
__device__ float    g_keysN[BC * DIMC];         // normalized keys
__device__ unsigned g_ctr = 0;                  // producer-completion counter

__device__ __forceinline__ void wait_ctr(unsigned target) {
    if (threadIdx.x == 0) {
        while (atomicAdd(&g_ctr, 0u) < target)
            __nanosleep(64);
        __threadfence();
    }
    __syncthreads();
}

__device__ __forceinline__ void ema_do(const float* __restrict__ pq,
                                       const float* __restrict__ pk,
                                       float* __restrict__ new_pk, int i) {
    float4 a  = __ldcs(reinterpret_cast<const float4*>(pq) + i);
    float4 b4 = __ldcs(reinterpret_cast<const float4*>(pk) + i);
    float4 r = make_float4(b4.x * 0.7f + a.x * 0.3f,
                           b4.y * 0.7f + a.y * 0.3f,
                           b4.z * 0.7f + a.z * 0.3f,
                           b4.w * 0.7f + a.w * 0.3f);
    __stcs(reinterpret_cast<float4*>(new_pk) + i, r);
}

// ---------------------------------------------------------------------------
// Single pool kernel. 11392 blocks x 256 threads.
// ---------------------------------------------------------------------------
__global__ __launch_bounds__(256) void moco_pool_kernel(
        const float* __restrict__ q,
        const int* __restrict__ sidx,
        const float* __restrict__ queue,
        const float* __restrict__ keys,
        const float* __restrict__ pq,
        const float* __restrict__ pk,
        const int* __restrict__ ptrp,
        float* __restrict__ logits,
        float* __restrict__ labels,
        float* __restrict__ new_queue,
        float* __restrict__ new_pk) {
    int bid = blockIdx.x;

    if (bid < NB_KEYN) {
        // ---- key-normalize producer: one warp per key row (8 rows/block) ----
        int gw   = bid * 8 + (threadIdx.x >> 5);   // 0..1023
        int lane = threadIdx.x & 31;
        float4 v = reinterpret_cast<const float4*>(keys + (size_t)gw * DIMC)[lane];
        float s = v.x * v.x + v.y * v.y + v.z * v.z + v.w * v.w;
        #pragma unroll
        for (int o = 16; o > 0; o >>= 1) s += __shfl_xor_sync(0xFFFFFFFFu, s, o);
        float inv = 1.0f / sqrtf(s);
        reinterpret_cast<float4*>(g_keysN + (size_t)gw * DIMC)[lane] =
            make_float4(v.x * inv, v.y * inv, v.z * inv, v.w * inv);
        __threadfence();
        __syncthreads();
        if (threadIdx.x == 0) atomicAdd(&g_ctr, 1u);

    } else if (bid < BID_EMA1) {
        // ---- transpose + new_queue producer: 32 k-cols x 128 dims ----
        __shared__ float tile[32][129];
        int tb   = bid - BID_TRANS;        // 0..2047
        int k0   = tb << 5;
        int lane = threadIdx.x & 31;
        int wy   = threadIdx.x >> 5;       // warp 0..7
        int ptr  = *ptrp;

        // Phase 1: load 128 rows x 32 cols (tile[k_local][d])
        #pragma unroll
        for (int i = 0; i < 16; ++i) {
            int d = wy * 16 + i;
            tile[lane][d] = __ldg(&queue[(size_t)d * KC + (k0 + lane)]);
        }
        __syncthreads();

        // Phase 2: fp16 transposed store of ORIGINAL values
        #pragma unroll
        for (int j = 0; j < 4; ++j) {
            int k = wy * 4 + j;
            float v0 = tile[k][4 * lane + 0];
            float v1 = tile[k][4 * lane + 1];
            float v2 = tile[k][4 * lane + 2];
            float v3 = tile[k][4 * lane + 3];
            __half2 h0 = __floats2half2_rn(v0, v1);
            __half2 h1 = __floats2half2_rn(v2, v3);
            uint2 pkt = make_uint2(*reinterpret_cast<unsigned*>(&h0),
                                   *reinterpret_cast<unsigned*>(&h1));
            *reinterpret_cast<uint2*>(&g_qTh[(size_t)(k0 + k) * DIMC + 4 * lane]) = pkt;
        }

        // signal qTh done for this block BEFORE the (rare) keysN wait
        __threadfence();
        __syncthreads();
        if (threadIdx.x == 0) atomicAdd(&g_ctr, 1u);

        // Phase 3: replaced columns <- normalized keys (only ~32 blocks hit this)
        int lo = ptr - k0;          if (lo < 0)  lo = 0;
        int hi = ptr + BC - k0;     if (hi > 32) hi = 32;
        if (lo < hi) {
            wait_ctr(CTR_KEYS);    // keyN blocks scheduled first; near-zero wait
            for (int k = lo + wy; k < hi; k += 8) {
                int r = k0 + k - ptr;
                float4 v = reinterpret_cast<const float4*>(g_keysN + (size_t)r * DIMC)[lane];
                tile[k][4 * lane + 0] = v.x;
                tile[k][4 * lane + 1] = v.y;
                tile[k][4 * lane + 2] = v.z;
                tile[k][4 * lane + 3] = v.w;
            }
            __syncthreads();
        }

        // Phase 4: write new_queue rows (streamed)
        #pragma unroll
        for (int i = 0; i < 16; ++i) {
            int d = wy * 16 + i;
            __stcs(&new_queue[(size_t)d * KC + (k0 + lane)], tile[lane][d]);
        }

    } else if (bid < BID_GATHER) {
        // ---- EMA stream, front slice ----
        ema_do(pq, pk, new_pk, (bid - BID_EMA1) * 256 + (int)threadIdx.x);

    } else if (bid < BID_EMA2) {
        // ---- logits gather consumer (R3 proven loop) ----
        int b = bid - BID_GATHER;
        __shared__ float4 qs4[32];
        int tid = threadIdx.x;
        if (tid < 32) {
            float4 v = reinterpret_cast<const float4*>(q + (size_t)b * DIMC)[tid];
            float s = v.x * v.x + v.y * v.y + v.z * v.z + v.w * v.w;
            #pragma unroll
            for (int o = 16; o > 0; o >>= 1) s += __shfl_xor_sync(0xFFFFFFFFu, s, o);
            float inv = 1.0f / sqrtf(s);
            qs4[tid] = make_float4(v.x * inv, v.y * inv, v.z * inv, v.w * inv);
        }
        if (tid == 0) labels[b] = 0.0f;

        wait_ctr(CTR_TRANS);   // transposes retire well before these blocks run

        int lane    = tid & 31;
        int warp    = tid >> 5;
        int half_id = lane >> 4;
        int subl    = lane & 15;

        float4 qa = qs4[subl * 2];
        float4 qb = qs4[subl * 2 + 1];

        const int* row = sidx + (size_t)b * LC;
        float* lrow = logits + (size_t)b * LC;

        #pragma unroll 4
        for (int l = warp * 2; l < LC; l += 16) {
            int idx = row[l + half_id];
            int4 pkt = reinterpret_cast<const int4*>(g_qTh + (size_t)idx * DIMC)[subl];
            float2 f0 = __half22float2(*reinterpret_cast<__half2*>(&pkt.x));
            float2 f1 = __half22float2(*reinterpret_cast<__half2*>(&pkt.y));
            float2 f2 = __half22float2(*reinterpret_cast<__half2*>(&pkt.z));
            float2 f3 = __half22float2(*reinterpret_cast<__half2*>(&pkt.w));
            float s = f0.x * qa.x + f0.y * qa.y + f1.x * qa.z + f1.y * qa.w
                    + f2.x * qb.x + f2.y * qb.y + f3.x * qb.z + f3.y * qb.w;
            #pragma unroll
            for (int o = 8; o > 0; o >>= 1)
                s += __shfl_xor_sync(0xFFFFFFFFu, s, o);
            if (subl == 0)
                lrow[l + half_id] = s * (1.0f / 0.09f);
        }

    } else {
        // ---- EMA stream, back slice ----
        int ema_id = NB_EMA1 + (bid - BID_EMA2);
        ema_do(pq, pk, new_pk, ema_id * 256 + (int)threadIdx.x);
    }
}

// ---------------------------------------------------------------------------
extern "C" void kernel_launch(void* const* d_in, const int* in_sizes, int n_in,
                              void* d_out, int out_size) {
    const float* q        = (const float*)d_in[0];
    const float* queue    = (const float*)d_in[1];
    const float* keys     = (const float*)d_in[2];
    const float* param_q  = (const float*)d_in[3];
    const float* param_k  = (const float*)d_in[4];
    const int*   sidx     = (const int*)  d_in[5];
    const int*   ptr      = (const int*)  d_in[6];

    float* out       = (float*)d_out;
    float* logits    = out;                            // B*L = 524288
    float* labels    = logits + (size_t)BC * LC;       // 1024
    float* new_queue = labels + BC;                    // DIM*K = 8388608
    float* new_pk    = new_queue + (size_t)DIMC * KC;  // P = 8388608

    // One launch: [keyN | trans(+copy) | EMA | gather | EMA]
    moco_pool_kernel<<<NB_TOTAL, 256>>>(
        q, sidx, queue, keys, param_q, param_k, ptr,
        logits, labels, new_queue, new_pk);
}